// round 8
// baseline (speedup 1.0000x reference)
#include <cuda_runtime.h>
#include <cuda_fp16.h>

// Problem shape (fixed by the dataset)
#define NN      50000
#define FIN     128
#define HF      128          // H * F_OUT
#define NHEAD   4
#define FOUT    32
#define EDGES   1600000
#define CAP     128          // slot capacity per dst (max degree ~60, Poisson(32))

// GEMM smem: 2 stages x (A chunk 64x36 + B chunk 32x136), floats
#define A_STRIDE 36
#define B_STRIDE 136
#define A_CHUNK  (64 * A_STRIDE)    // 2304 floats
#define B_CHUNK  (32 * B_STRIDE)    // 4352 floats
#define STAGE    (A_CHUNK + B_CHUNK)
#define GEMM_SMEM_BYTES (2 * STAGE * 4)   // 53,248 B

// ---------------- scratch (static __device__, no allocation) ----------------
__device__ __align__(16) __half g_key[NN * HF];      // 12.8 MB, L2-resident
__device__ __align__(16) float  g_sdst[NN * NHEAD];  // 800 KB
__device__ __align__(16) float  g_ssrc[NN * NHEAD];  // 800 KB
__device__ int g_counts[NN];                         // per-dst fill cursor
__device__ int g_slots[NN * CAP];                    // 25.6 MB: src lists per dst

// ---------------------------------------------------------------------------
// helpers
// ---------------------------------------------------------------------------
// rna-equivalent tf32 rounding: add half-ulp of bit 13 to the raw fp32 bits.
// (carry propagates correctly into the exponent; inputs are finite/normal)
__device__ __forceinline__ unsigned rnd13(unsigned u) { return u + 0x1000u; }

__device__ __forceinline__ void mma_tf32(float c[4], const unsigned a[4], const unsigned b[2])
{
    asm volatile(
        "mma.sync.aligned.m16n8k8.row.col.f32.tf32.tf32.f32 "
        "{%0,%1,%2,%3}, {%4,%5,%6,%7}, {%8,%9}, {%0,%1,%2,%3};\n"
        : "+f"(c[0]), "+f"(c[1]), "+f"(c[2]), "+f"(c[3])
        : "r"(a[0]), "r"(a[1]), "r"(a[2]), "r"(a[3]), "r"(b[0]), "r"(b[1]));
}

__device__ __forceinline__ void cp16(float* s, const float* g)
{
    unsigned sa = (unsigned)__cvta_generic_to_shared(s);
    asm volatile("cp.async.cg.shared.global [%0], [%1], 16;\n" :: "r"(sa), "l"(g));
}
__device__ __forceinline__ void cp_commit()
{
    asm volatile("cp.async.commit_group;\n");
}
template <int N>
__device__ __forceinline__ void cp_wait()
{
    asm volatile("cp.async.wait_group %0;\n" :: "n"(N));
}

// ---------------------------------------------------------------------------
// 1) tf32 GEMM, 64x128 block tile (3 CTA/SM), cp.async double buffer.
//    8 warps in 4x2: wm = (wid&3)*16 rows, wn = (wid>>2)*64 cols.
//    Fused epilogue: +bias, fp16 key store, attention dots.
// ---------------------------------------------------------------------------
__global__ void __launch_bounds__(256)
gemm_kernel(const float* __restrict__ A,
            const float* __restrict__ W,
            const float* __restrict__ bias,
            const float* __restrict__ a_w,
            int n)
{
    extern __shared__ float smem[];

    const int tid   = threadIdx.x;
    const int lane  = tid & 31;
    const int wid   = tid >> 5;
    const int wm    = (wid & 3) * 16;
    const int wn    = (wid >> 2) * 64;
    const int g     = lane >> 2;
    const int tg    = lane & 3;
    const int rowB  = blockIdx.x * 64;

    // cp.async decomposition
    const int ar = tid >> 2;                 // A: row 0..63 (4 thr/row)
    const int ac = (tid & 3) * 8;            // A: col 0,8,16,24 (2 cp16 each)
    const int br = tid >> 3;                 // B: row 0..31  (8 thr/row)
    const int bc = (tid & 7) * 16;           // B: col, 4 cp16 each

    auto load_chunk = [&](int kc, int stage) {
        float* As = smem + stage * STAGE;
        float* Bs = As + A_CHUNK;
        int gr = rowB + ar;
        if (gr < n) {
            cp16(&As[ar * A_STRIDE + ac],     &A[gr * FIN + kc * 32 + ac]);
            cp16(&As[ar * A_STRIDE + ac + 4], &A[gr * FIN + kc * 32 + ac + 4]);
        } else {
            *(float4*)&As[ar * A_STRIDE + ac]     = make_float4(0.f,0.f,0.f,0.f);
            *(float4*)&As[ar * A_STRIDE + ac + 4] = make_float4(0.f,0.f,0.f,0.f);
        }
        cp16(&Bs[br * B_STRIDE + bc],      &W[(kc * 32 + br) * HF + bc]);
        cp16(&Bs[br * B_STRIDE + bc + 4],  &W[(kc * 32 + br) * HF + bc + 4]);
        cp16(&Bs[br * B_STRIDE + bc + 8],  &W[(kc * 32 + br) * HF + bc + 8]);
        cp16(&Bs[br * B_STRIDE + bc + 12], &W[(kc * 32 + br) * HF + bc + 12]);
    };

    load_chunk(0, 0);
    cp_commit();

    float acc[8][4];
#pragma unroll
    for (int nt = 0; nt < 8; nt++)
#pragma unroll
        for (int r = 0; r < 4; r++) acc[nt][r] = 0.f;

    for (int kc = 0; kc < 4; kc++) {
        if (kc < 3) {
            load_chunk(kc + 1, (kc + 1) & 1);
            cp_commit();
            cp_wait<1>();
        } else {
            cp_wait<0>();
        }
        __syncthreads();

        const unsigned* Au = (const unsigned*)(smem + (kc & 1) * STAGE);
        const unsigned* Bu = Au + A_CHUNK;

#pragma unroll
        for (int ks = 0; ks < 4; ks++) {
            int kk = ks * 8;
            unsigned a[4];
            a[0] = rnd13(Au[(wm + g) * A_STRIDE + kk + tg]);
            a[1] = rnd13(Au[(wm + g + 8) * A_STRIDE + kk + tg]);
            a[2] = rnd13(Au[(wm + g) * A_STRIDE + kk + tg + 4]);
            a[3] = rnd13(Au[(wm + g + 8) * A_STRIDE + kk + tg + 4]);
            unsigned b[8][2];
#pragma unroll
            for (int nt = 0; nt < 8; nt++) {
                int col = wn + nt * 8 + g;
                b[nt][0] = rnd13(Bu[(kk + tg) * B_STRIDE + col]);
                b[nt][1] = rnd13(Bu[(kk + tg + 4) * B_STRIDE + col]);
            }
#pragma unroll
            for (int nt = 0; nt < 8; nt++)
                mma_tf32(acc[nt], a, b[nt]);
        }
        __syncthreads();
    }

    // ---- epilogue: bias, fp16 store, fused attention dots ----
    // rows: wm+g (hf=0), wm+g+8 (hf=1); cols wn..wn+63 (2 heads, hl 0/1)
    float sd[2][2], ss[2][2];
#pragma unroll
    for (int hf = 0; hf < 2; hf++)
#pragma unroll
        for (int hl = 0; hl < 2; hl++) { sd[hf][hl] = 0.f; ss[hf][hl] = 0.f; }

#pragma unroll
    for (int nt = 0; nt < 8; nt++) {
        int cbase = wn + nt * 8 + tg * 2;
        int hl    = nt >> 2;
        int head  = (wn >> 5) + hl;
        int cin   = cbase & 31;
        float b0 = __ldg(&bias[cbase]);
        float b1 = __ldg(&bias[cbase + 1]);
        float ad0 = __ldg(&a_w[head * 64 + cin]);
        float ad1 = __ldg(&a_w[head * 64 + cin + 1]);
        float as0 = __ldg(&a_w[head * 64 + 32 + cin]);
        float as1 = __ldg(&a_w[head * 64 + 32 + cin + 1]);

        int row0 = rowB + wm + g;
        float v00 = acc[nt][0] + b0;
        float v01 = acc[nt][1] + b1;
        float v10 = acc[nt][2] + b0;
        float v11 = acc[nt][3] + b1;
        if (row0 < n)
            *(__half2*)&g_key[row0 * HF + cbase] = __floats2half2_rn(v00, v01);
        if (row0 + 8 < n)
            *(__half2*)&g_key[(row0 + 8) * HF + cbase] = __floats2half2_rn(v10, v11);
        sd[0][hl] += v00 * ad0 + v01 * ad1;
        sd[1][hl] += v10 * ad0 + v11 * ad1;
        ss[0][hl] += v00 * as0 + v01 * as1;
        ss[1][hl] += v10 * as0 + v11 * as1;
    }
#pragma unroll
    for (int o = 1; o <= 2; o <<= 1) {
#pragma unroll
        for (int hf = 0; hf < 2; hf++)
#pragma unroll
            for (int hl = 0; hl < 2; hl++) {
                sd[hf][hl] += __shfl_xor_sync(0xFFFFFFFFu, sd[hf][hl], o);
                ss[hf][hl] += __shfl_xor_sync(0xFFFFFFFFu, ss[hf][hl], o);
            }
    }
    if (tg == 0) {
#pragma unroll
        for (int hf = 0; hf < 2; hf++) {
            int row = rowB + wm + g + hf * 8;
            if (row < n) {
#pragma unroll
                for (int hl = 0; hl < 2; hl++) {
                    int head = (wn >> 5) + hl;
                    g_sdst[row * NHEAD + head] = sd[hf][hl];
                    g_ssrc[row * NHEAD + head] = ss[hf][hl];
                }
            }
        }
    }
}

// ---------------------------------------------------------------------------
// 2) single-pass bucket scatter
// ---------------------------------------------------------------------------
__global__ void scatter_kernel(const int4* __restrict__ esrc4,
                               const int4* __restrict__ edst4, int e4)
{
    int i = blockIdx.x * blockDim.x + threadIdx.x;
    if (i >= e4) return;
    int4 s = esrc4[i];
    int4 d = edst4[i];
    int p;
    p = atomicAdd(&g_counts[d.x], 1); if (p < CAP) g_slots[d.x * CAP + p] = s.x;
    p = atomicAdd(&g_counts[d.y], 1); if (p < CAP) g_slots[d.y * CAP + p] = s.y;
    p = atomicAdd(&g_counts[d.z], 1); if (p < CAP) g_slots[d.z * CAP + p] = s.z;
    p = atomicAdd(&g_counts[d.w], 1); if (p < CAP) g_slots[d.w * CAP + p] = s.w;
}

// ---------------------------------------------------------------------------
// 3) fused single-pass softmax + aggregation: one warp per dst node,
//    4-edge unrolled with aligned int4 slot loads (broadcast).
// ---------------------------------------------------------------------------
__global__ void __launch_bounds__(256)
agg_kernel(const float* __restrict__ a_b, float* __restrict__ out, int n)
{
    int node = blockIdx.x * 8 + (threadIdx.x >> 5);
    if (node >= n) return;
    int lane = threadIdx.x & 31;
    int h    = lane >> 3;

    const __half* keyb = g_key + lane * 4;
    float base_s = g_sdst[node * NHEAD + h] + __ldg(&a_b[h]);

    float acc0, acc1, acc2, acc3, dsum;
    {   // self edge
        float v = base_s + g_ssrc[node * NHEAD + h];
        v = fmaxf(v, 0.2f * v);
        float w = __expf(v);
        uint2 kk = *(const uint2*)&keyb[node * HF];
        float2 f0 = __half22float2(*(__half2*)&kk.x);
        float2 f1 = __half22float2(*(__half2*)&kk.y);
        acc0 = w * f0.x; acc1 = w * f0.y; acc2 = w * f1.x; acc3 = w * f1.y;
        dsum = w;
    }

    int cnt = min(g_counts[node], CAP);
    const int* slots = &g_slots[node * CAP];   // 512B-aligned

    float b0 = 0.f, b1 = 0.f, b2 = 0.f, b3 = 0.f, bsum = 0.f;
    int i = 0;
    for (; i + 4 <= cnt; i += 4) {
        int4 s4 = __ldg((const int4*)&slots[i]);      // one LDG.128 broadcast
        float v0 = base_s + __ldg(&g_ssrc[s4.x * NHEAD + h]);
        float v1 = base_s + __ldg(&g_ssrc[s4.y * NHEAD + h]);
        float v2 = base_s + __ldg(&g_ssrc[s4.z * NHEAD + h]);
        float v3 = base_s + __ldg(&g_ssrc[s4.w * NHEAD + h]);
        uint2 k0 = *(const uint2*)&keyb[s4.x * HF];
        uint2 k1 = *(const uint2*)&keyb[s4.y * HF];
        uint2 k2 = *(const uint2*)&keyb[s4.z * HF];
        uint2 k3 = *(const uint2*)&keyb[s4.w * HF];
        v0 = fmaxf(v0, 0.2f * v0);
        v1 = fmaxf(v1, 0.2f * v1);
        v2 = fmaxf(v2, 0.2f * v2);
        v3 = fmaxf(v3, 0.2f * v3);
        float w0 = __expf(v0);
        float w1 = __expf(v1);
        float w2 = __expf(v2);
        float w3 = __expf(v3);
        float2 a00 = __half22float2(*(__half2*)&k0.x);
        float2 a01 = __half22float2(*(__half2*)&k0.y);
        float2 a10 = __half22float2(*(__half2*)&k1.x);
        float2 a11 = __half22float2(*(__half2*)&k1.y);
        float2 a20 = __half22float2(*(__half2*)&k2.x);
        float2 a21 = __half22float2(*(__half2*)&k2.y);
        float2 a30 = __half22float2(*(__half2*)&k3.x);
        float2 a31 = __half22float2(*(__half2*)&k3.y);
        acc0 += w0 * a00.x; acc1 += w0 * a00.y; acc2 += w0 * a01.x; acc3 += w0 * a01.y;
        b0   += w1 * a10.x; b1   += w1 * a10.y; b2   += w1 * a11.x; b3   += w1 * a11.y;
        acc0 += w2 * a20.x; acc1 += w2 * a20.y; acc2 += w2 * a21.x; acc3 += w2 * a21.y;
        b0   += w3 * a30.x; b1   += w3 * a30.y; b2   += w3 * a31.x; b3   += w3 * a31.y;
        dsum += w0 + w2; bsum += w1 + w3;
    }
    for (; i < cnt; i++) {
        int s = __ldg(&slots[i]);
        float v = base_s + __ldg(&g_ssrc[s * NHEAD + h]);
        v = fmaxf(v, 0.2f * v);
        float w = __expf(v);
        uint2 kk = *(const uint2*)&keyb[s * HF];
        float2 f0 = __half22float2(*(__half2*)&kk.x);
        float2 f1 = __half22float2(*(__half2*)&kk.y);
        acc0 += w * f0.x; acc1 += w * f0.y; acc2 += w * f1.x; acc3 += w * f1.y;
        dsum += w;
    }

    acc0 += b0; acc1 += b1; acc2 += b2; acc3 += b3; dsum += bsum;

    float inv = __frcp_rn(dsum);
    float4 o = make_float4(acc0 * inv, acc1 * inv, acc2 * inv, acc3 * inv);
    *(float4*)&out[node * HF + lane * 4] = o;
}

// ---------------------------------------------------------------------------
extern "C" void kernel_launch(void* const* d_in, const int* in_sizes, int n_in,
                              void* d_out, int out_size)
{
    const float* features = (const float*)d_in[0];
    const int*   esrc     = (const int*)d_in[1];
    const int*   edst     = (const int*)d_in[2];
    const float* Ww       = (const float*)d_in[3];
    const float* Wb       = (const float*)d_in[4];
    const float* aw       = (const float*)d_in[5];
    const float* ab       = (const float*)d_in[6];
    float*       out      = (float*)d_out;

    int n = in_sizes[0] / FIN;   // 50000
    int e = in_sizes[1];         // 1600000 (divisible by 4)
    int e4 = e >> 2;

    cudaFuncSetAttribute(gemm_kernel,
                         cudaFuncAttributeMaxDynamicSharedMemorySize,
                         GEMM_SMEM_BYTES);

    void* counts_ptr = nullptr;
    cudaGetSymbolAddress(&counts_ptr, g_counts);
    cudaMemsetAsync(counts_ptr, 0, n * sizeof(int));

    gemm_kernel<<<(n + 63) / 64, 256, GEMM_SMEM_BYTES>>>(features, Ww, Wb, aw, n);
    scatter_kernel<<<(e4 + 255) / 256, 256>>>((const int4*)esrc, (const int4*)edst, e4);
    agg_kernel<<<(n + 7) / 8, 256>>>(ab, out, n);
}

// round 9
// speedup vs baseline: 1.1375x; 1.1375x over previous
#include <cuda_runtime.h>
#include <cuda_fp16.h>

// Problem shape (fixed by the dataset)
#define NN      50000
#define FIN     128
#define HF      128          // H * F_OUT
#define NHEAD   4
#define FOUT    32
#define EDGES   1600000
#define CAP     128          // slot capacity per dst (max degree ~60, Poisson(32))

// GEMM smem: A tile 128x136 halves + B tile 128x136 halves (col-major)
#define T_STRIDE 136
#define TILE_HALVES (128 * T_STRIDE)            // 17408
#define GEMM_SMEM_BYTES (2 * TILE_HALVES * 2)   // 69,632 B

// ---------------- scratch (static __device__, no allocation) ----------------
__device__ __align__(16) __half g_key[NN * HF];      // 12.8 MB, L2-resident
__device__ __align__(16) float  g_sdst[NN * NHEAD];  // 800 KB
__device__ __align__(16) float  g_ssrc[NN * NHEAD];  // 800 KB
__device__ __align__(16) __half g_Wh[TILE_HALVES];   // W, fp16, col-major padded
__device__ int g_counts[NN];                         // per-dst fill cursor
__device__ int g_slots[NN * CAP];                    // 25.6 MB: src lists per dst

// ---------------------------------------------------------------------------
// helpers
// ---------------------------------------------------------------------------
__device__ __forceinline__ void mma_f16(float c[4], const unsigned a[4], const unsigned b[2])
{
    asm volatile(
        "mma.sync.aligned.m16n8k16.row.col.f32.f16.f16.f32 "
        "{%0,%1,%2,%3}, {%4,%5,%6,%7}, {%8,%9}, {%0,%1,%2,%3};\n"
        : "+f"(c[0]), "+f"(c[1]), "+f"(c[2]), "+f"(c[3])
        : "r"(a[0]), "r"(a[1]), "r"(a[2]), "r"(a[3]), "r"(b[0]), "r"(b[1]));
}

__device__ __forceinline__ void cp16(void* s, const void* g)
{
    unsigned sa = (unsigned)__cvta_generic_to_shared(s);
    asm volatile("cp.async.cg.shared.global [%0], [%1], 16;\n" :: "r"(sa), "l"(g));
}
__device__ __forceinline__ void cp_commit()
{
    asm volatile("cp.async.commit_group;\n");
}
__device__ __forceinline__ void cp_wait_all()
{
    asm volatile("cp.async.wait_group 0;\n");
}

// ---------------------------------------------------------------------------
// 0) prep: W (128x128 fp32, row-major k x col) -> g_Wh (col-major fp16,
//    stride 136). Coalesced 2B writes; strided reads (64KB total, trivial).
// ---------------------------------------------------------------------------
__global__ void prep_w_kernel(const float* __restrict__ W)
{
    int t = blockIdx.x * blockDim.x + threadIdx.x;    // 0..16383
    int c = t >> 7, k = t & 127;
    g_Wh[c * T_STRIDE + k] = __float2half(W[k * HF + c]);
}

// ---------------------------------------------------------------------------
// 1) fp16 tensor-core GEMM, 128x128 tile, whole-K resident in smem.
//    B arrives pre-converted via cp.async; A converted on load (STS.64).
//    8 warps in 4x2: wm=(wid&3)*32 rows, wn=(wid>>2)*64 cols.
//    Fused epilogue: +bias, fp16 key store, attention dots.
// ---------------------------------------------------------------------------
__global__ void __launch_bounds__(256, 2)
gemm_kernel(const float* __restrict__ A,
            const float* __restrict__ bias,
            const float* __restrict__ a_w,
            int n)
{
    extern __shared__ __half smh[];
    __half* As = smh;                  // [row][k], stride 136
    __half* Bh = smh + TILE_HALVES;    // [col][k], stride 136

    const int tid   = threadIdx.x;
    const int lane  = tid & 31;
    const int wid   = tid >> 5;
    const int wm    = (wid & 3) * 32;
    const int wn    = (wid >> 2) * 64;
    const int g     = lane >> 2;
    const int tg    = lane & 3;
    const int rowB  = blockIdx.x * 128;

    // ---- B: flat async copy of pre-converted W (34,816 B = 2176 x 16B) ----
    {
        const char* src = (const char*)g_Wh;
        char* dst = (char*)Bh;
#pragma unroll
        for (int j = 0; j < 9; j++) {
            int lin = j * 256 + tid;
            if (lin < 2176) cp16(dst + lin * 16, src + lin * 16);
        }
        cp_commit();
    }

    // ---- A: load fp32, convert to fp16, STS.64 (conflict-free) ----
#pragma unroll
    for (int j = 0; j < 16; j++) {
        int lin = j * 256 + tid;
        int r = lin >> 5, c4 = (lin & 31) << 2;
        int gr = rowB + r;
        float4 v = (gr < n) ? *(const float4*)&A[gr * FIN + c4]
                            : make_float4(0.f, 0.f, 0.f, 0.f);
        __half2 h0 = __floats2half2_rn(v.x, v.y);
        __half2 h1 = __floats2half2_rn(v.z, v.w);
        uint2 u;
        u.x = *(unsigned*)&h0;
        u.y = *(unsigned*)&h1;
        *(uint2*)&As[r * T_STRIDE + c4] = u;
    }

    cp_wait_all();
    __syncthreads();

    float acc[2][8][4];
#pragma unroll
    for (int mt = 0; mt < 2; mt++)
#pragma unroll
        for (int nt = 0; nt < 8; nt++)
#pragma unroll
            for (int r = 0; r < 4; r++) acc[mt][nt][r] = 0.f;

    // ---- main loop: 8 k-steps of 16 ----
#pragma unroll
    for (int ks = 0; ks < 8; ks++) {
        int kk = ks * 16;
        unsigned a[2][4];
#pragma unroll
        for (int mt = 0; mt < 2; mt++) {
            int r0 = wm + mt * 16;
            a[mt][0] = *(const unsigned*)&As[(r0 + g)     * T_STRIDE + kk + 2 * tg];
            a[mt][1] = *(const unsigned*)&As[(r0 + g + 8) * T_STRIDE + kk + 2 * tg];
            a[mt][2] = *(const unsigned*)&As[(r0 + g)     * T_STRIDE + kk + 8 + 2 * tg];
            a[mt][3] = *(const unsigned*)&As[(r0 + g + 8) * T_STRIDE + kk + 8 + 2 * tg];
        }
        unsigned b[8][2];
#pragma unroll
        for (int nt = 0; nt < 8; nt++) {
            int col = wn + nt * 8 + g;
            b[nt][0] = *(const unsigned*)&Bh[col * T_STRIDE + kk + 2 * tg];
            b[nt][1] = *(const unsigned*)&Bh[col * T_STRIDE + kk + 8 + 2 * tg];
        }
#pragma unroll
        for (int mt = 0; mt < 2; mt++)
#pragma unroll
            for (int nt = 0; nt < 8; nt++)
                mma_f16(acc[mt][nt], a[mt], b[nt]);
    }

    // ---- epilogue: bias, fp16 store, fused attention dots ----
    float sd[2][2][2], ss[2][2][2];
#pragma unroll
    for (int mt = 0; mt < 2; mt++)
#pragma unroll
        for (int hf = 0; hf < 2; hf++)
#pragma unroll
            for (int hl = 0; hl < 2; hl++) { sd[mt][hf][hl] = 0.f; ss[mt][hf][hl] = 0.f; }

#pragma unroll
    for (int nt = 0; nt < 8; nt++) {
        int cbase = wn + nt * 8 + tg * 2;
        int hl    = nt >> 2;
        int head  = (wn >> 5) + hl;
        int cin   = cbase & 31;
        float b0 = __ldg(&bias[cbase]);
        float b1 = __ldg(&bias[cbase + 1]);
        float ad0 = __ldg(&a_w[head * 64 + cin]);
        float ad1 = __ldg(&a_w[head * 64 + cin + 1]);
        float as0 = __ldg(&a_w[head * 64 + 32 + cin]);
        float as1 = __ldg(&a_w[head * 64 + 32 + cin + 1]);
#pragma unroll
        for (int mt = 0; mt < 2; mt++) {
            int row0 = rowB + wm + mt * 16 + g;
            float v00 = acc[mt][nt][0] + b0;
            float v01 = acc[mt][nt][1] + b1;
            float v10 = acc[mt][nt][2] + b0;
            float v11 = acc[mt][nt][3] + b1;
            if (row0 < n)
                *(__half2*)&g_key[row0 * HF + cbase] = __floats2half2_rn(v00, v01);
            if (row0 + 8 < n)
                *(__half2*)&g_key[(row0 + 8) * HF + cbase] = __floats2half2_rn(v10, v11);
            sd[mt][0][hl] += v00 * ad0 + v01 * ad1;
            sd[mt][1][hl] += v10 * ad0 + v11 * ad1;
            ss[mt][0][hl] += v00 * as0 + v01 * as1;
            ss[mt][1][hl] += v10 * as0 + v11 * as1;
        }
    }
#pragma unroll
    for (int o = 1; o <= 2; o <<= 1) {
#pragma unroll
        for (int mt = 0; mt < 2; mt++)
#pragma unroll
            for (int hf = 0; hf < 2; hf++)
#pragma unroll
                for (int hl = 0; hl < 2; hl++) {
                    sd[mt][hf][hl] += __shfl_xor_sync(0xFFFFFFFFu, sd[mt][hf][hl], o);
                    ss[mt][hf][hl] += __shfl_xor_sync(0xFFFFFFFFu, ss[mt][hf][hl], o);
                }
    }
    if (tg == 0) {
#pragma unroll
        for (int mt = 0; mt < 2; mt++)
#pragma unroll
            for (int hf = 0; hf < 2; hf++) {
                int row = rowB + wm + mt * 16 + g + hf * 8;
                if (row < n) {
#pragma unroll
                    for (int hl = 0; hl < 2; hl++) {
                        int head = (wn >> 5) + hl;
                        g_sdst[row * NHEAD + head] = sd[mt][hf][hl];
                        g_ssrc[row * NHEAD + head] = ss[mt][hf][hl];
                    }
                }
            }
    }
}

// ---------------------------------------------------------------------------
// 2) single-pass bucket scatter
// ---------------------------------------------------------------------------
__global__ void scatter_kernel(const int4* __restrict__ esrc4,
                               const int4* __restrict__ edst4, int e4)
{
    int i = blockIdx.x * blockDim.x + threadIdx.x;
    if (i >= e4) return;
    int4 s = esrc4[i];
    int4 d = edst4[i];
    int p;
    p = atomicAdd(&g_counts[d.x], 1); if (p < CAP) g_slots[d.x * CAP + p] = s.x;
    p = atomicAdd(&g_counts[d.y], 1); if (p < CAP) g_slots[d.y * CAP + p] = s.y;
    p = atomicAdd(&g_counts[d.z], 1); if (p < CAP) g_slots[d.z * CAP + p] = s.z;
    p = atomicAdd(&g_counts[d.w], 1); if (p < CAP) g_slots[d.w * CAP + p] = s.w;
}

// ---------------------------------------------------------------------------
// 3) fused single-pass softmax + aggregation: one warp per dst node.
//    (exact form from the 116.7us best measurement)
// ---------------------------------------------------------------------------
__global__ void __launch_bounds__(128)
agg_kernel(const float* __restrict__ a_b, float* __restrict__ out, int n)
{
    int node = blockIdx.x * 4 + (threadIdx.x >> 5);
    if (node >= n) return;
    int lane = threadIdx.x & 31;
    int h    = lane >> 3;

    const __half* keyb = g_key + lane * 4;
    float base_s = g_sdst[node * NHEAD + h] + __ldg(&a_b[h]);

    float acc0, acc1, acc2, acc3, dsum;
    {   // self edge
        float v = base_s + g_ssrc[node * NHEAD + h];
        v = fmaxf(v, 0.2f * v);
        float w = __expf(v);
        uint2 kk = *(const uint2*)&keyb[node * HF];
        float2 f0 = __half22float2(*(__half2*)&kk.x);
        float2 f1 = __half22float2(*(__half2*)&kk.y);
        acc0 = w * f0.x; acc1 = w * f0.y; acc2 = w * f1.x; acc3 = w * f1.y;
        dsum = w;
    }

    int cnt = min(g_counts[node], CAP);
    const int* slots = &g_slots[node * CAP];

    float b0 = 0.f, b1 = 0.f, b2 = 0.f, b3 = 0.f, bsum = 0.f;
    int i = 0;
#pragma unroll 2
    for (; i + 2 <= cnt; i += 2) {
        int s0 = __ldg(&slots[i]);
        int s1 = __ldg(&slots[i + 1]);
        float v0 = base_s + __ldg(&g_ssrc[s0 * NHEAD + h]);
        float v1 = base_s + __ldg(&g_ssrc[s1 * NHEAD + h]);
        uint2 k0 = *(const uint2*)&keyb[s0 * HF];
        uint2 k1 = *(const uint2*)&keyb[s1 * HF];
        v0 = fmaxf(v0, 0.2f * v0);
        v1 = fmaxf(v1, 0.2f * v1);
        float w0 = __expf(v0);
        float w1 = __expf(v1);
        float2 a00 = __half22float2(*(__half2*)&k0.x);
        float2 a01 = __half22float2(*(__half2*)&k0.y);
        float2 a10 = __half22float2(*(__half2*)&k1.x);
        float2 a11 = __half22float2(*(__half2*)&k1.y);
        acc0 += w0 * a00.x; acc1 += w0 * a00.y; acc2 += w0 * a01.x; acc3 += w0 * a01.y;
        b0   += w1 * a10.x; b1   += w1 * a10.y; b2   += w1 * a11.x; b3   += w1 * a11.y;
        dsum += w0; bsum += w1;
    }
    if (i < cnt) {
        int s = __ldg(&slots[i]);
        float v = base_s + __ldg(&g_ssrc[s * NHEAD + h]);
        v = fmaxf(v, 0.2f * v);
        float w = __expf(v);
        uint2 kk = *(const uint2*)&keyb[s * HF];
        float2 f0 = __half22float2(*(__half2*)&kk.x);
        float2 f1 = __half22float2(*(__half2*)&kk.y);
        acc0 += w * f0.x; acc1 += w * f0.y; acc2 += w * f1.x; acc3 += w * f1.y;
        dsum += w;
    }

    acc0 += b0; acc1 += b1; acc2 += b2; acc3 += b3; dsum += bsum;

    float inv = __frcp_rn(dsum);
    float4 o = make_float4(acc0 * inv, acc1 * inv, acc2 * inv, acc3 * inv);
    *(float4*)&out[node * HF + lane * 4] = o;
}

// ---------------------------------------------------------------------------
extern "C" void kernel_launch(void* const* d_in, const int* in_sizes, int n_in,
                              void* d_out, int out_size)
{
    const float* features = (const float*)d_in[0];
    const int*   esrc     = (const int*)d_in[1];
    const int*   edst     = (const int*)d_in[2];
    const float* Ww       = (const float*)d_in[3];
    const float* Wb       = (const float*)d_in[4];
    const float* aw       = (const float*)d_in[5];
    const float* ab       = (const float*)d_in[6];
    float*       out      = (float*)d_out;

    int n = in_sizes[0] / FIN;   // 50000
    int e = in_sizes[1];         // 1600000 (divisible by 4)
    int e4 = e >> 2;

    cudaFuncSetAttribute(gemm_kernel,
                         cudaFuncAttributeMaxDynamicSharedMemorySize,
                         GEMM_SMEM_BYTES);

    void* counts_ptr = nullptr;
    cudaGetSymbolAddress(&counts_ptr, g_counts);
    cudaMemsetAsync(counts_ptr, 0, n * sizeof(int));

    prep_w_kernel<<<64, 256>>>(Ww);
    gemm_kernel<<<(n + 127) / 128, 256, GEMM_SMEM_BYTES>>>(features, Wb, aw, n);
    scatter_kernel<<<(e4 + 255) / 256, 256>>>((const int4*)esrc, (const int4*)edst, e4);
    agg_kernel<<<(n + 3) / 4, 128>>>(ab, out, n);
}